// round 1
// baseline (speedup 1.0000x reference)
#include <cuda_runtime.h>

#define BATCH 16
#define NPTS  1024
#define CDIM  64

// Scratch (allocation-free rule: __device__ globals)
__device__ float g_y[BATCH * NPTS * CDIM];   // x @ W_rel
__device__ float g_r[BATCH * NPTS * CDIM];   // x @ W_root + b_rel

// ---------------------------------------------------------------------------
// Stage 1: y = x @ W_rel ; r = x @ W_root + b_rel
// One block per 64 rows of the flattened (B*N, 64) x matrix. 256 threads,
// 4x4 micro-tiles. x tile stored TRANSPOSED in smem so the k-loop reads are
// contiguous float4 (conflict-free).
// ---------------------------------------------------------------------------
__global__ __launch_bounds__(256) void stage1_kernel(
    const float* __restrict__ x,
    const float* __restrict__ W_rel,
    const float* __restrict__ b_rel,
    const float* __restrict__ W_root)
{
    __shared__ float xs[64][64];   // xs[k][row]  (transposed)
    __shared__ float wr[64][64];   // W_rel[k][col]
    __shared__ float wo[64][64];   // W_root[k][col]

    const int tid  = threadIdx.x;
    const int row0 = blockIdx.x * 64;        // global row in [0, B*N)

    // Load weight matrices (row-major, float4)
    for (int t = tid; t < 64 * 16; t += 256) {
        const int r  = t >> 4;
        const int c4 = (t & 15) << 2;
        *(float4*)&wr[r][c4] = *(const float4*)&W_rel[r * 64 + c4];
        *(float4*)&wo[r][c4] = *(const float4*)&W_root[r * 64 + c4];
    }
    // Load x tile, store transposed
    for (int t = tid; t < 64 * 16; t += 256) {
        const int r  = t >> 4;
        const int c4 = (t & 15) << 2;
        float4 v = *(const float4*)&x[(row0 + r) * 64 + c4];
        xs[c4 + 0][r] = v.x;
        xs[c4 + 1][r] = v.y;
        xs[c4 + 2][r] = v.z;
        xs[c4 + 3][r] = v.w;
    }
    __syncthreads();

    const int ty = tid >> 4;   // 0..15 -> rows ty*4..ty*4+3
    const int tx = tid & 15;   // 0..15 -> cols tx*4..tx*4+3

    float accY[4][4] = {};
    float accR[4][4] = {};

#pragma unroll 8
    for (int k = 0; k < 64; k++) {
        const float4 a  = *(const float4*)&xs[k][ty * 4];
        const float4 by = *(const float4*)&wr[k][tx * 4];
        const float4 br = *(const float4*)&wo[k][tx * 4];
        const float av[4]  = {a.x, a.y, a.z, a.w};
        const float byv[4] = {by.x, by.y, by.z, by.w};
        const float brv[4] = {br.x, br.y, br.z, br.w};
#pragma unroll
        for (int r = 0; r < 4; r++)
#pragma unroll
            for (int c = 0; c < 4; c++) {
                accY[r][c] = fmaf(av[r], byv[c], accY[r][c]);
                accR[r][c] = fmaf(av[r], brv[c], accR[r][c]);
            }
    }

    float4 brel = *(const float4*)&b_rel[tx * 4];
    const float brelv[4] = {brel.x, brel.y, brel.z, brel.w};

#pragma unroll
    for (int r = 0; r < 4; r++) {
        const int grow = row0 + ty * 4 + r;
        float4 oy, orr;
        oy.x = accY[r][0]; oy.y = accY[r][1]; oy.z = accY[r][2]; oy.w = accY[r][3];
        orr.x = accR[r][0] + brelv[0];
        orr.y = accR[r][1] + brelv[1];
        orr.z = accR[r][2] + brelv[2];
        orr.w = accR[r][3] + brelv[3];
        *(float4*)&g_y[grow * 64 + tx * 4] = oy;
        *(float4*)&g_r[grow * 64 + tx * 4] = orr;
    }
}

// ---------------------------------------------------------------------------
// Stage 2: out[b] = (adj[b] * w_edge[ea[b]]) @ y[b] + r[b]
// One block per (batch, 64-row tile): 256 blocks. 256 threads, 4x4 micro.
// a_s kept [row][j] with pad 68: float4 stores conflict-free, column reads
// (4x LDS.32, 8 distinct banks in warp) conflict-free. y_s[j][col] pad 68:
// LDS.128 row reads conflict-free.
// ---------------------------------------------------------------------------
__global__ __launch_bounds__(256) void stage2_kernel(
    const float* __restrict__ adj,
    const int*   __restrict__ ea,
    const float* __restrict__ w_edge,
    float*       __restrict__ out)
{
    __shared__ float a_s[64][68];
    __shared__ float y_s[64][68];
    __shared__ float we[4];

    const int tid = threadIdx.x;
    const int b   = blockIdx.x >> 4;
    const int it  = blockIdx.x & 15;
    const int i0  = it * 64;

    if (tid < 4) we[tid] = w_edge[tid];

    const long adjBase = (long)b * NPTS * NPTS;
    const int  ty = tid >> 4;
    const int  tx = tid & 15;

    float acc[4][4] = {};

    for (int jt = 0; jt < 16; jt++) {
        __syncthreads();   // protects previous-iteration reads (and we[] on jt=0)
        const int j0 = jt * 64;

        // Build a_s = adj * w_edge[ea] for this [64 x 64] tile
        for (int t = tid; t < 1024; t += 256) {
            const int r  = t >> 4;
            const int c4 = (t & 15) << 2;
            const long g = adjBase + (long)(i0 + r) * NPTS + j0 + c4;
            const float4 av = *(const float4*)&adj[g];
            const int4   ev = *(const int4*)&ea[g];
            float4 w;
            w.x = av.x * we[ev.x];
            w.y = av.y * we[ev.y];
            w.z = av.z * we[ev.z];
            w.w = av.w * we[ev.w];
            *(float4*)&a_s[r][c4] = w;
        }
        // Load y tile [j][k]
        for (int t = tid; t < 1024; t += 256) {
            const int r  = t >> 4;
            const int c4 = (t & 15) << 2;
            *(float4*)&y_s[r][c4] =
                *(const float4*)&g_y[((b * NPTS) + j0 + r) * 64 + c4];
        }
        __syncthreads();

#pragma unroll 8
        for (int k = 0; k < 64; k++) {
            const float a0 = a_s[ty * 4 + 0][k];
            const float a1 = a_s[ty * 4 + 1][k];
            const float a2 = a_s[ty * 4 + 2][k];
            const float a3 = a_s[ty * 4 + 3][k];
            const float4 yv = *(const float4*)&y_s[k][tx * 4];
            acc[0][0] = fmaf(a0, yv.x, acc[0][0]);
            acc[0][1] = fmaf(a0, yv.y, acc[0][1]);
            acc[0][2] = fmaf(a0, yv.z, acc[0][2]);
            acc[0][3] = fmaf(a0, yv.w, acc[0][3]);
            acc[1][0] = fmaf(a1, yv.x, acc[1][0]);
            acc[1][1] = fmaf(a1, yv.y, acc[1][1]);
            acc[1][2] = fmaf(a1, yv.z, acc[1][2]);
            acc[1][3] = fmaf(a1, yv.w, acc[1][3]);
            acc[2][0] = fmaf(a2, yv.x, acc[2][0]);
            acc[2][1] = fmaf(a2, yv.y, acc[2][1]);
            acc[2][2] = fmaf(a2, yv.z, acc[2][2]);
            acc[2][3] = fmaf(a2, yv.w, acc[2][3]);
            acc[3][0] = fmaf(a3, yv.x, acc[3][0]);
            acc[3][1] = fmaf(a3, yv.y, acc[3][1]);
            acc[3][2] = fmaf(a3, yv.z, acc[3][2]);
            acc[3][3] = fmaf(a3, yv.w, acc[3][3]);
        }
    }

    // Epilogue: add r = x@W_root + b_rel, write out
    const int grow0 = b * NPTS + i0;
#pragma unroll
    for (int r = 0; r < 4; r++) {
        const int grow = grow0 + ty * 4 + r;
        const float4 rv = *(const float4*)&g_r[grow * 64 + tx * 4];
        float4 o;
        o.x = acc[r][0] + rv.x;
        o.y = acc[r][1] + rv.y;
        o.z = acc[r][2] + rv.z;
        o.w = acc[r][3] + rv.w;
        *(float4*)&out[grow * 64 + tx * 4] = o;
    }
}

extern "C" void kernel_launch(void* const* d_in, const int* in_sizes, int n_in,
                              void* d_out, int out_size)
{
    const float* x      = (const float*)d_in[0];
    const float* adj    = (const float*)d_in[1];
    const int*   ea     = (const int*)d_in[2];
    const float* W_rel  = (const float*)d_in[3];
    const float* b_rel  = (const float*)d_in[4];
    const float* W_root = (const float*)d_in[5];
    const float* w_edge = (const float*)d_in[6];
    float* out = (float*)d_out;

    stage1_kernel<<<(BATCH * NPTS) / 64, 256>>>(x, W_rel, b_rel, W_root);
    stage2_kernel<<<BATCH * (NPTS / 64), 256>>>(adj, ea, w_edge, out);
}

// round 3
// speedup vs baseline: 1.9672x; 1.9672x over previous
#include <cuda_runtime.h>
#include <cuda_bf16.h>

#define BATCH 16
#define NPTS  1024
#define CDIM  64

// -------- scratch (__device__ globals, allocation-free rule) --------
__device__ float         g_r[BATCH * NPTS * CDIM];      // x@W_root + b_rel (fp32)
__device__ __nv_bfloat16 g_yT_hi[BATCH * CDIM * NPTS];  // (x@W_rel)^T hi, [b][c][j]
__device__ __nv_bfloat16 g_yT_lo[BATCH * CDIM * NPTS];  // lo residual

// ===================== helpers =====================
__device__ __forceinline__ unsigned smem_u32(const void* p) {
    unsigned a;
    asm("{ .reg .u64 t; cvta.to.shared.u64 t, %1; cvt.u32.u64 %0, t; }"
        : "=r"(a) : "l"(p));
    return a;
}
#define CP_ASYNC16(dst, src) \
    asm volatile("cp.async.cg.shared.global [%0], [%1], 16;" :: "r"(dst), "l"(src))
#define CP_COMMIT() asm volatile("cp.async.commit_group;" ::: "memory")
#define STS128(addr, r0, r1, r2, r3) \
    asm volatile("st.shared.v4.b32 [%0], {%1,%2,%3,%4};" \
                 :: "r"(addr), "r"(r0), "r"(r1), "r"(r2), "r"(r3) : "memory")

__device__ __forceinline__ unsigned swz(unsigned off) { return off ^ ((off >> 3) & 0x70); }

__device__ __forceinline__ void ldx4(unsigned* r, unsigned addr) {
    asm volatile("ldmatrix.sync.aligned.m8n8.x4.shared.b16 {%0,%1,%2,%3}, [%4];"
                 : "=r"(r[0]), "=r"(r[1]), "=r"(r[2]), "=r"(r[3]) : "r"(addr));
}
__device__ __forceinline__ void mma16816(float* d, const unsigned* a,
                                         unsigned b0, unsigned b1) {
    asm volatile("mma.sync.aligned.m16n8k16.row.col.f32.bf16.bf16.f32 "
                 "{%0,%1,%2,%3}, {%4,%5,%6,%7}, {%8,%9}, {%0,%1,%2,%3};"
                 : "+f"(d[0]), "+f"(d[1]), "+f"(d[2]), "+f"(d[3])
                 : "r"(a[0]), "r"(a[1]), "r"(a[2]), "r"(a[3]), "r"(b0), "r"(b1));
}

// ===================== Stage 1 =====================
// y = x@W_rel (-> transposed bf16 hi/lo), r = x@W_root + b_rel (fp32)
__global__ __launch_bounds__(256) void stage1_kernel(
    const float* __restrict__ x, const float* __restrict__ W_rel,
    const float* __restrict__ b_rel, const float* __restrict__ W_root)
{
    __shared__ float xs[64][64];   // transposed x tile
    __shared__ float wr[64][64];
    __shared__ float wo[64][64];

    const int tid  = threadIdx.x;
    const int row0 = blockIdx.x * 64;

    for (int t = tid; t < 64 * 16; t += 256) {
        const int r = t >> 4, c4 = (t & 15) << 2;
        *(float4*)&wr[r][c4] = *(const float4*)&W_rel[r * 64 + c4];
        *(float4*)&wo[r][c4] = *(const float4*)&W_root[r * 64 + c4];
    }
    for (int t = tid; t < 64 * 16; t += 256) {
        const int r = t >> 4, c4 = (t & 15) << 2;
        float4 v = *(const float4*)&x[(row0 + r) * 64 + c4];
        xs[c4 + 0][r] = v.x; xs[c4 + 1][r] = v.y;
        xs[c4 + 2][r] = v.z; xs[c4 + 3][r] = v.w;
    }
    __syncthreads();

    const int ty = tid >> 4, tx = tid & 15;
    float accY[4][4] = {}, accR[4][4] = {};

#pragma unroll 8
    for (int k = 0; k < 64; k++) {
        const float4 a  = *(const float4*)&xs[k][ty * 4];
        const float4 by = *(const float4*)&wr[k][tx * 4];
        const float4 br = *(const float4*)&wo[k][tx * 4];
        const float av[4]  = {a.x, a.y, a.z, a.w};
        const float byv[4] = {by.x, by.y, by.z, by.w};
        const float brv[4] = {br.x, br.y, br.z, br.w};
#pragma unroll
        for (int r = 0; r < 4; r++)
#pragma unroll
            for (int c = 0; c < 4; c++) {
                accY[r][c] = fmaf(av[r], byv[c], accY[r][c]);
                accR[r][c] = fmaf(av[r], brv[c], accR[r][c]);
            }
    }

    float4 brel = *(const float4*)&b_rel[tx * 4];
    const float brelv[4] = {brel.x, brel.y, brel.z, brel.w};

    const int b  = row0 >> 10;
    const int jg = (row0 & 1023) + ty * 4;

#pragma unroll
    for (int r = 0; r < 4; r++) {
        const int grow = row0 + ty * 4 + r;
        float4 orr;
        orr.x = accR[r][0] + brelv[0]; orr.y = accR[r][1] + brelv[1];
        orr.z = accR[r][2] + brelv[2]; orr.w = accR[r][3] + brelv[3];
        *(float4*)&g_r[grow * 64 + tx * 4] = orr;
    }
#pragma unroll
    for (int c = 0; c < 4; c++) {
        unsigned hp[2], lp[2];
#pragma unroll
        for (int p = 0; p < 2; p++) {
            float v0 = accY[2 * p + 0][c], v1 = accY[2 * p + 1][c];
            __nv_bfloat16 h0 = __float2bfloat16(v0);
            __nv_bfloat16 h1 = __float2bfloat16(v1);
            __nv_bfloat16 l0 = __float2bfloat16(v0 - __bfloat162float(h0));
            __nv_bfloat16 l1 = __float2bfloat16(v1 - __bfloat162float(h1));
            hp[p] = (unsigned)__bfloat16_as_ushort(h0) | ((unsigned)__bfloat16_as_ushort(h1) << 16);
            lp[p] = (unsigned)__bfloat16_as_ushort(l0) | ((unsigned)__bfloat16_as_ushort(l1) << 16);
        }
        const long idx = ((long)(b * 64 + tx * 4 + c) << 10) + jg;
        *(uint2*)&g_yT_hi[idx] = make_uint2(hp[0], hp[1]);
        *(uint2*)&g_yT_lo[idx] = make_uint2(lp[0], lp[1]);
    }
}

// ===================== Stage 2 =====================
// out[b, i0:i0+64, :] = (adj*we[ea]) @ y + r  via mma.sync bf16-split
#define NCHUNK 16
// dyn smem: A stage s(0,1): s*16384 (hi 8K + lo 8K); B stage u(0..2): 32768+u*16384
#define SMEM_A(s) ((s) * 16384)
#define SMEM_B(u) (32768 + (u) * 16384)
#define SMEM_DYN  81920

struct Chunk { float4 a[4]; int4 e[4]; };

__device__ __forceinline__ void issue_B(unsigned sbase, int u, int b, int j0, int tid) {
#pragma unroll
    for (int v = 0; v < 4; v++) {
        const int idx  = tid + v * 256;     // 0..1023
        const int tile = idx >> 9;          // 0 hi, 1 lo
        const int row  = (idx >> 3) & 63;   // n (0..63)
        const int cb   = idx & 7;
        const __nv_bfloat16* src =
            (tile ? g_yT_lo : g_yT_hi) + (((long)(b * 64 + row)) << 10) + j0 + cb * 8;
        const unsigned dst = sbase + SMEM_B(u) + tile * 8192 + swz(row * 128 + cb * 16);
        CP_ASYNC16(dst, src);
    }
}

__device__ __forceinline__ void ldg_chunk(const float* __restrict__ adj,
                                          const int* __restrict__ ea,
                                          long rowbase, int j0, int jb, Chunk& c) {
#pragma unroll
    for (int q = 0; q < 4; q++) {
        const long off = rowbase + j0 + jb + q * 4;
        c.a[q] = __ldg((const float4*)(adj + off));
        c.e[q] = __ldg((const int4*)(ea + off));
    }
}

__device__ __forceinline__ float wsel(int e, float w0, float w1, float w2, float w3) {
    return e == 0 ? w0 : (e == 1 ? w1 : (e == 2 ? w2 : w3));
}

__device__ __forceinline__ void convert_sts(unsigned abase, int row, int jb,
                                            float w0, float w1, float w2, float w3,
                                            const Chunk& c) {
    unsigned hp[8], lp[8];
#pragma unroll
    for (int q = 0; q < 4; q++) {
        const float av[4] = {c.a[q].x, c.a[q].y, c.a[q].z, c.a[q].w};
        const int   ev[4] = {c.e[q].x, c.e[q].y, c.e[q].z, c.e[q].w};
#pragma unroll
        for (int p = 0; p < 2; p++) {
            float v0 = av[2 * p + 0] * wsel(ev[2 * p + 0], w0, w1, w2, w3);
            float v1 = av[2 * p + 1] * wsel(ev[2 * p + 1], w0, w1, w2, w3);
            __nv_bfloat16 h0 = __float2bfloat16(v0);
            __nv_bfloat16 h1 = __float2bfloat16(v1);
            __nv_bfloat16 l0 = __float2bfloat16(v0 - __bfloat162float(h0));
            __nv_bfloat16 l1 = __float2bfloat16(v1 - __bfloat162float(h1));
            hp[q * 2 + p] = (unsigned)__bfloat16_as_ushort(h0) |
                            ((unsigned)__bfloat16_as_ushort(h1) << 16);
            lp[q * 2 + p] = (unsigned)__bfloat16_as_ushort(l0) |
                            ((unsigned)__bfloat16_as_ushort(l1) << 16);
        }
    }
    const unsigned o = row * 128 + jb * 2;
    STS128(abase + swz(o),          hp[0], hp[1], hp[2], hp[3]);
    STS128(abase + swz(o + 16),     hp[4], hp[5], hp[6], hp[7]);
    STS128(abase + 8192 + swz(o),      lp[0], lp[1], lp[2], lp[3]);
    STS128(abase + 8192 + swz(o + 16), lp[4], lp[5], lp[6], lp[7]);
}

__device__ __forceinline__ void compute_chunk(
    unsigned aHi, unsigned bHi,
    unsigned aRowOff, unsigned aColX, unsigned bRowOff, unsigned bColX,
    float acc[4][4])
{
#pragma unroll
    for (int kh = 0; kh < 2; kh++) {
        unsigned ah[2][4], al[2][4], bb[4][4];
        // A frags: kt = 2kh, 2kh+1 ; colbyte = kt*32 + (mA>>1)*16
        ldx4(ah[0], aHi + aRowOff + (((2 * kh + 0) * 32) ^ aColX));
        ldx4(ah[1], aHi + aRowOff + (((2 * kh + 1) * 32) ^ aColX));
        ldx4(al[0], aHi + 8192 + aRowOff + (((2 * kh + 0) * 32) ^ aColX));
        ldx4(al[1], aHi + 8192 + aRowOff + (((2 * kh + 1) * 32) ^ aColX));
        // B hi frags: nt rows, colbyte = kh*64 + mB*16
#pragma unroll
        for (int nt = 0; nt < 4; nt++)
            ldx4(bb[nt], bHi + bRowOff + nt * 1024 + ((kh * 64) ^ bColX));
#pragma unroll
        for (int kt2 = 0; kt2 < 2; kt2++)
#pragma unroll
            for (int nt = 0; nt < 4; nt++) {
                mma16816(acc[nt], ah[kt2], bb[nt][kt2 * 2], bb[nt][kt2 * 2 + 1]);
                mma16816(acc[nt], al[kt2], bb[nt][kt2 * 2], bb[nt][kt2 * 2 + 1]);
            }
        // B lo frags (reuse bb)
#pragma unroll
        for (int nt = 0; nt < 4; nt++)
            ldx4(bb[nt], bHi + 8192 + bRowOff + nt * 1024 + ((kh * 64) ^ bColX));
#pragma unroll
        for (int kt2 = 0; kt2 < 2; kt2++)
#pragma unroll
            for (int nt = 0; nt < 4; nt++)
                mma16816(acc[nt], ah[kt2], bb[nt][kt2 * 2], bb[nt][kt2 * 2 + 1]);
    }
}

__global__ __launch_bounds__(256, 2) void stage2_kernel(
    const float* __restrict__ adj, const int* __restrict__ ea,
    const float* __restrict__ w_edge, float* __restrict__ out)
{
    extern __shared__ char smem_raw[];
    const unsigned sbase = smem_u32(smem_raw);

    const int tid  = threadIdx.x;
    const int lane = tid & 31, wid = tid >> 5;
    const int wi = wid >> 1, wn = wid & 1;          // warp tile: rows wi*16, cols wn*32
    const int b  = blockIdx.x >> 4;
    const int i0 = (blockIdx.x & 15) * 64;

    const float w0 = __ldg(w_edge + 0), w1 = __ldg(w_edge + 1),
                w2 = __ldg(w_edge + 2), w3 = __ldg(w_edge + 3);

    // A producer mapping
    const int  row = tid >> 2;               // 0..63
    const int  jb  = (tid & 3) << 4;         // 0,16,32,48
    const long rowbase = ((long)b << 20) + (long)(i0 + row) * NPTS;

    // ldmatrix per-lane address components
    const int l8 = lane & 7, mm = lane >> 3;
    const int arow = wi * 16 + (mm & 1) * 8 + l8;
    const unsigned aRowOff = (unsigned)arow * 128;
    const unsigned aColX   = ((unsigned)(mm >> 1) * 16) ^ ((unsigned)l8 << 4);
    const int brow = wn * 32 + l8;
    const unsigned bRowOff = (unsigned)brow * 128;
    const unsigned bColX   = ((unsigned)mm * 16) ^ ((unsigned)l8 << 4);

    float acc[4][4] = {};

    Chunk c0, c1;
    issue_B(sbase, 0, b, 0, tid);
    CP_COMMIT();
    ldg_chunk(adj, ea, rowbase, 0, jb, c0);

#pragma unroll 1
    for (int t2 = 0; t2 < NCHUNK; t2 += 2) {
#pragma unroll
        for (int h = 0; h < 2; h++) {
            const int t = t2 + h;
            Chunk& cur = h ? c1 : c0;
            Chunk& nxt = h ? c0 : c1;
            const bool more = (t + 1 < NCHUNK);
            if (more) {
                issue_B(sbase, (t + 1) % 3, b, (t + 1) * 64, tid);
                CP_COMMIT();
                ldg_chunk(adj, ea, rowbase, (t + 1) * 64, jb, nxt);
            }
            convert_sts(sbase + SMEM_A(t & 1), row, jb, w0, w1, w2, w3, cur);
            if (more) asm volatile("cp.async.wait_group 1;" ::: "memory");
            else      asm volatile("cp.async.wait_group 0;" ::: "memory");
            __syncthreads();
            compute_chunk(sbase + SMEM_A(t & 1), sbase + SMEM_B(t % 3),
                          aRowOff, aColX, bRowOff, bColX, acc);
        }
    }

    // epilogue: add r, store
    const int gid = lane >> 2, tig = lane & 3;
    const int grow = b * NPTS + i0 + wi * 16 + gid;
#pragma unroll
    for (int nt = 0; nt < 4; nt++) {
        const int col = wn * 32 + nt * 8 + tig * 2;
        const long idx0 = (long)grow * 64 + col;
        const long idx1 = (long)(grow + 8) * 64 + col;
        const float2 r0 = *(const float2*)&g_r[idx0];
        const float2 r1 = *(const float2*)&g_r[idx1];
        float2 o0, o1;
        o0.x = acc[nt][0] + r0.x; o0.y = acc[nt][1] + r0.y;
        o1.x = acc[nt][2] + r1.x; o1.y = acc[nt][3] + r1.y;
        *(float2*)&out[idx0] = o0;
        *(float2*)&out[idx1] = o1;
    }
}

// ===================== launch =====================
extern "C" void kernel_launch(void* const* d_in, const int* in_sizes, int n_in,
                              void* d_out, int out_size)
{
    const float* x      = (const float*)d_in[0];
    const float* adj    = (const float*)d_in[1];
    const int*   ea     = (const int*)d_in[2];
    const float* W_rel  = (const float*)d_in[3];
    const float* b_rel  = (const float*)d_in[4];
    const float* W_root = (const float*)d_in[5];
    const float* w_edge = (const float*)d_in[6];
    float* out = (float*)d_out;

    static bool attr_set = false;
    if (!attr_set) {
        cudaFuncSetAttribute(stage2_kernel,
                             cudaFuncAttributeMaxDynamicSharedMemorySize, SMEM_DYN);
        attr_set = true;
    }

    stage1_kernel<<<(BATCH * NPTS) / 64, 256>>>(x, W_rel, b_rel, W_root);
    stage2_kernel<<<BATCH * (NPTS / 64), 256, SMEM_DYN>>>(adj, ea, w_edge, out);
}